// round 5
// baseline (speedup 1.0000x reference)
#include <cuda_runtime.h>
#include <math.h>

#define BB 64
#define SS 512
#define HH 1024
#define LL 64
#define NEM (BB * SS * LL)

__device__ float g_em[NEM];   // raw emissions scratch (for CRF numerator)
__device__ float g_E[NEM];    // exp(emissions)
__device__ float g_llh[BB];

// ---- f32x2 helpers -------------------------------------------------------
union F4U { float4 v; float f[4]; unsigned long long u[2]; };

__device__ __forceinline__ void ffma2(unsigned long long& d,
                                      unsigned long long a,
                                      unsigned long long b) {
    asm("fma.rn.f32x2 %0, %1, %2, %0;" : "+l"(d) : "l"(a), "l"(b));
}
__device__ __forceinline__ float lo2(unsigned long long x) {
    return __uint_as_float((unsigned)(x & 0xffffffffull));
}
__device__ __forceinline__ float hi2(unsigned long long x) {
    return __uint_as_float((unsigned)(x >> 32));
}
__device__ __forceinline__ unsigned long long pack2(float a, float b) {
    return (unsigned long long)__float_as_uint(a) |
           ((unsigned long long)__float_as_uint(b) << 32);
}

// ---------------------------------------------------------------------------
// GEMM: em[m][l] = sum_h hs[m][h]*W[h][l] + b[l].
// Tile 128x64, 256 threads, 8x4 micro-tile, K-tile 32.
// FFMA2 paired over K: acc2 holds (even-k, odd-k) partial sums.
// Epilogue writes em to out_em (d_out+1) and g_em, exp(em) to g_E.
// ---------------------------------------------------------------------------
#define ASTR 36
#define BSTR 36

__global__ __launch_bounds__(256, 2) void gemm_kernel(
    const float* __restrict__ hs, const float* __restrict__ W,
    const float* __restrict__ bias,
    float* __restrict__ out_em, float* __restrict__ em2, float* __restrict__ Eo)
{
    __shared__ __align__(16) float As[128 * ASTR];  // [m][k], padded
    __shared__ __align__(16) float Bs[64 * BSTR];   // [n][k] (transposed), padded

    const int tid = threadIdx.x;
    const int tc = tid & 15;    // cols tc*4 .. +3
    const int tr = tid >> 4;    // rows tr*8 .. +7
    const int m0 = blockIdx.x * 128;

    unsigned long long acc[8][4];
#pragma unroll
    for (int r = 0; r < 8; r++)
#pragma unroll
        for (int c = 0; c < 4; c++) acc[r][c] = 0ull;

    for (int k0 = 0; k0 < HH; k0 += 32) {
        __syncthreads();
        // A tile: 128 rows x 32 k = 1024 float4 quads
#pragma unroll
        for (int p = 0; p < 4; p++) {
            int q = tid + p * 256;
            int row = q >> 3;
            int kq = q & 7;
            float4 v = *(const float4*)&hs[(size_t)(m0 + row) * HH + k0 + kq * 4];
            *(float4*)&As[row * ASTR + kq * 4] = v;
        }
        // B tile transposed: W[k][n] -> Bs[n][k], 2048 scalars
#pragma unroll
        for (int p = 0; p < 8; p++) {
            int idx = tid + p * 256;
            int r = idx >> 6;
            int c = idx & 63;
            Bs[c * BSTR + r] = W[(size_t)(k0 + r) * LL + c];
        }
        __syncthreads();

#pragma unroll
        for (int kq = 0; kq < 8; kq++) {
            F4U b[4];
#pragma unroll
            for (int c = 0; c < 4; c++)
                b[c].v = *(const float4*)&Bs[(tc * 4 + c) * BSTR + kq * 4];
#pragma unroll
            for (int r = 0; r < 8; r++) {
                F4U a;
                a.v = *(const float4*)&As[(tr * 8 + r) * ASTR + kq * 4];
#pragma unroll
                for (int c = 0; c < 4; c++) {
                    ffma2(acc[r][c], a.u[0], b[c].u[0]);
                    ffma2(acc[r][c], a.u[1], b[c].u[1]);
                }
            }
        }
    }

    float bj[4];
#pragma unroll
    for (int c = 0; c < 4; c++) bj[c] = bias[tc * 4 + c];
#pragma unroll
    for (int r = 0; r < 8; r++) {
        size_t base = (size_t)(m0 + tr * 8 + r) * LL + tc * 4;
#pragma unroll
        for (int c = 0; c < 4; c++) {
            float e = lo2(acc[r][c]) + hi2(acc[r][c]) + bj[c];
            out_em[base + c] = e;
            em2[base + c] = e;
            Eo[base + c] = expf(e);
        }
    }
}

// ---------------------------------------------------------------------------
// CRF: linear-space forward scan. 64 blocks x 64 threads (j = tid).
//   w_j(t) = (sum_i w_i(t-1) * P_ij) * E_j(t),  P = exp(trans)
// Renormalize by w_0 every 8 steps; log-scale tracked per-thread.
// E streamed via double-buffered smem chunks of 32 steps.
// ---------------------------------------------------------------------------
__device__ __forceinline__ int tag_of(int x) {
    int t = (x == -100) ? 0 : x;
    return max(0, min(LL - 1, t));
}

__global__ __launch_bounds__(64) void crf_kernel(
    const float* __restrict__ em_all,   // g_em (raw emissions)
    const float* __restrict__ E_all,    // g_E  (exp emissions)
    const int* __restrict__ mask,
    const int* __restrict__ labels,
    const float* __restrict__ start_t,
    const float* __restrict__ end_t,
    const float* __restrict__ trans)
{
    const int b = blockIdx.x;
    const int j = threadIdx.x;           // 0..63

    const float* em = em_all + (size_t)b * (SS * LL);
    const float* Ee = E_all + (size_t)b * (SS * LL);
    const int* msk = mask + b * SS;
    const int* lab = labels + (size_t)b * SS;

    __shared__ __align__(16) float4 u_sh[2][16];        // double-buffered w vector
    __shared__ __align__(16) float4 Esm[2][512];        // 2 x 32 steps x 64 states
    __shared__ float red[64];
    __shared__ int len_sh;
    __shared__ float num_sh;

    // ---- sequence length (contiguous prefix mask) ----
    int cnt = 0;
    for (int t = j; t < SS; t += 64) cnt += msk[t];
    red[j] = (float)cnt;
    __syncthreads();
#pragma unroll
    for (int s = 32; s > 0; s >>= 1) {
        if (j < s) red[j] += red[j + s];
        __syncthreads();
    }
    if (j == 0) len_sh = max(1, min(SS, (int)(red[0] + 0.5f)));
    __syncthreads();
    const int len = len_sh;

    // ---- numerator ----
    float nsum = 0.f;
    for (int t = 1 + j; t < len; t += 64) {
        int tp = tag_of(lab[t - 1]);
        int tc = tag_of(lab[t]);
        nsum += trans[tp * LL + tc] + em[t * LL + tc];
    }
    __syncthreads();
    red[j] = nsum;
    __syncthreads();
#pragma unroll
    for (int s = 32; s > 0; s >>= 1) {
        if (j < s) red[j] += red[j + s];
        __syncthreads();
    }
    if (j == 0) {
        int t0 = tag_of(lab[0]);
        int tl = tag_of(lab[len - 1]);
        num_sh = start_t[t0] + em[t0] + red[0] + end_t[tl];
    }

    // ---- P packed as f32x2 pairs over i: P2[q] = (P[2q][j], P[2q+1][j]) ----
    unsigned long long P2[32];
#pragma unroll
    for (int q = 0; q < 32; q++)
        P2[q] = pack2(__expf(trans[(2 * q) * LL + j]),
                      __expf(trans[(2 * q + 1) * LL + j]));

    // ---- load E chunk 0 (t = 0..31) ----
#pragma unroll
    for (int p = 0; p < 8; p++) {
        int idx = p * 64 + j;                     // quad id 0..511
        Esm[0][idx] = *(const float4*)&Ee[(size_t)idx * 4];
    }
    __syncthreads();

    // ---- init: w_j(0) = exp(start_j) * E_j(0) ----
    float w = __expf(start_t[j]) * ((const float*)Esm[0])[j];
    ((float*)u_sh[0])[j] = w;
    float logshift = 0.f;

    const int nchunks = (len + 31) >> 5;
    for (int ch = 0; ch < nchunks; ch++) {
        // prefetch next chunk into the other buffer (loads hidden under compute)
        if (ch + 1 < nchunks) {
            int t0n = (ch + 1) << 5;
            int nq = min(512, (len - t0n) * 16);
#pragma unroll
            for (int p = 0; p < 8; p++) {
                int idx = p * 64 + j;
                if (idx < nq)
                    Esm[(ch + 1) & 1][idx] =
                        *(const float4*)&Ee[(size_t)t0n * 64 + (size_t)idx * 4];
            }
        }
        const float* Ep = (const float*)Esm[ch & 1];
        int tA = (ch == 0) ? 1 : (ch << 5);
        int tB = min(len, (ch + 1) << 5);

        for (int t = tA; t < tB; t++) {
            __syncthreads();   // u_sh[(t-1)&1] visible to all
            const float4* U = u_sh[(t - 1) & 1];
            float u0 = ((const float*)U)[0];

            unsigned long long a0 = 0ull, a1 = 0ull, a2 = 0ull, a3 = 0ull;
#pragma unroll
            for (int q4 = 0; q4 < 16; q4 += 2) {
                F4U ua, ub;
                ua.v = U[q4];
                ub.v = U[q4 + 1];
                ffma2(a0, ua.u[0], P2[2 * q4 + 0]);
                ffma2(a1, ua.u[1], P2[2 * q4 + 1]);
                ffma2(a2, ub.u[0], P2[2 * q4 + 2]);
                ffma2(a3, ub.u[1], P2[2 * q4 + 3]);
            }
            float r = (lo2(a0) + hi2(a0)) + (lo2(a1) + hi2(a1)) +
                      (lo2(a2) + hi2(a2)) + (lo2(a3) + hi2(a3));
            float e = Ep[((t & 31) << 6) + j];
            float wn = r * e;
            if ((t & 7) == 0) {          // renormalize by w_0(t-1)
                wn *= __frcp_rn(u0);
                logshift += __logf(u0);
            }
            w = wn;
            ((float*)u_sh[t & 1])[j] = w;
        }
        __syncthreads();   // chunk boundary: prefetch STS drained, reads done
    }

    // ---- log Z ----
    red[j] = w * __expf(end_t[j]);
    __syncthreads();
#pragma unroll
    for (int s = 32; s > 0; s >>= 1) {
        if (j < s) red[j] += red[j + s];
        __syncthreads();
    }
    if (j == 0) {
        float log_z = __logf(red[0]) + logshift;
        g_llh[b] = num_sh - log_z;
    }
}

// ---------------------------------------------------------------------------
__global__ void loss_kernel(float* __restrict__ out) {
    int t = threadIdx.x;   // 32 threads
    float v = g_llh[t] + g_llh[t + 32];
#pragma unroll
    for (int o = 16; o > 0; o >>= 1) v += __shfl_down_sync(0xffffffffu, v, o);
    if (t == 0) out[0] = -v * (1.0f / BB);
}

// ---------------------------------------------------------------------------
extern "C" void kernel_launch(void* const* d_in, const int* in_sizes, int n_in,
                              void* d_out, int out_size)
{
    const float* hs      = (const float*)d_in[0];   // [B,S,H] f32
    const int* mask      = (const int*)d_in[1];     // [B,S]   i32
    const int* labels    = (const int*)d_in[2];     // [B,S]   i32
    const float* W       = (const float*)d_in[3];   // [H,L]   f32
    const float* bias    = (const float*)d_in[4];   // [L]
    const float* start_t = (const float*)d_in[5];   // [L]
    const float* end_t   = (const float*)d_in[6];   // [L]
    const float* trans   = (const float*)d_in[7];   // [L,L]
    float* out = (float*)d_out;    // out[0]=loss, out[1..]=emissions

    float* em_scratch = nullptr;
    float* E_scratch = nullptr;
    cudaGetSymbolAddress((void**)&em_scratch, g_em);
    cudaGetSymbolAddress((void**)&E_scratch, g_E);

    gemm_kernel<<<256, 256>>>(hs, W, bias, out + 1, em_scratch, E_scratch);
    crf_kernel<<<BB, 64>>>(em_scratch, E_scratch, mask, labels,
                           start_t, end_t, trans);
    loss_kernel<<<1, 32>>>(out);
}

// round 6
// speedup vs baseline: 1.3075x; 1.3075x over previous
#include <cuda_runtime.h>
#include <math.h>

#define BB 64
#define SS 512
#define HH 1024
#define LL 64
#define NEM (BB * SS * LL)

__device__ float g_E[NEM];    // exp(emissions)
__device__ float g_llh[BB];

// ---- f32x2 helpers -------------------------------------------------------
union F4U { float4 v; float f[4]; unsigned long long u[2]; };

__device__ __forceinline__ void ffma2(unsigned long long& d,
                                      unsigned long long a,
                                      unsigned long long b) {
    asm("fma.rn.f32x2 %0, %1, %2, %0;" : "+l"(d) : "l"(a), "l"(b));
}
__device__ __forceinline__ unsigned long long dup2(float a) {
    unsigned long long d;
    asm("mov.b64 %0, {%1, %1};" : "=l"(d) : "r"(__float_as_uint(a)));
    return d;
}
__device__ __forceinline__ float lo2(unsigned long long x) {
    return __uint_as_float((unsigned)(x & 0xffffffffull));
}
__device__ __forceinline__ float hi2(unsigned long long x) {
    return __uint_as_float((unsigned)(x >> 32));
}
__device__ __forceinline__ unsigned long long pack2(float a, float b) {
    return (unsigned long long)__float_as_uint(a) |
           ((unsigned long long)__float_as_uint(b) << 32);
}

// ---------------------------------------------------------------------------
// GEMM: em[m][l] = sum_h hs[m][h]*W[h][l] + b[l]
// Tile 128x64, 128 threads, 8x8 micro-tile, K-tile 32, grid 256.
// FFMA2 paired over N: acc u64 = (col 2c, col 2c+1).
//   As: k-major [k][132]  (A-frag = 2 LDS.128, ~1 line each)
//   Bs: row-major [k][64] (B-frag = 2 LDS.128, 2 lines each)
// ---------------------------------------------------------------------------
#define ASTR 132

__global__ __launch_bounds__(128) void gemm_kernel(
    const float* __restrict__ hs, const float* __restrict__ W,
    const float* __restrict__ bias,
    float* __restrict__ out_em, float* __restrict__ Eo)
{
    __shared__ __align__(16) float As[32 * ASTR];   // [k][m], m padded to 132
    __shared__ __align__(16) float Bs[32 * 64];     // [k][n]

    const int tid = threadIdx.x;
    const int tc = tid & 7;     // col group: cols tc*8 .. +7 (4 u64 pairs)
    const int tr = tid >> 3;    // row group: rows tr*8 .. +7
    const int m0 = blockIdx.x * 128;

    unsigned long long acc[8][4];
#pragma unroll
    for (int r = 0; r < 8; r++)
#pragma unroll
        for (int c = 0; c < 4; c++) acc[r][c] = 0ull;

    for (int k0 = 0; k0 < HH; k0 += 32) {
        __syncthreads();
        // A tile: 128 m x 32 k, transposed into As[k][m]
#pragma unroll
        for (int p = 0; p < 8; p++) {
            int q = tid + p * 128;          // quad id 0..1023
            int row = q >> 3;               // m 0..127
            int kq = q & 7;                 // k-quad 0..7
            float4 v = *(const float4*)&hs[(size_t)(m0 + row) * HH + k0 + kq * 4];
            As[(kq * 4 + 0) * ASTR + row] = v.x;
            As[(kq * 4 + 1) * ASTR + row] = v.y;
            As[(kq * 4 + 2) * ASTR + row] = v.z;
            As[(kq * 4 + 3) * ASTR + row] = v.w;
        }
        // B tile: 32 k x 64 n, row-major
#pragma unroll
        for (int p = 0; p < 4; p++) {
            int idx = tid + p * 128;        // quad id 0..511
            int r = idx >> 4;               // k 0..31
            int c4 = idx & 15;              // col quad
            float4 v = *(const float4*)&W[(size_t)(k0 + r) * LL + c4 * 4];
            *(float4*)&Bs[r * 64 + c4 * 4] = v;
        }
        __syncthreads();

#pragma unroll 4
        for (int k = 0; k < 32; k++) {
            F4U b0, b1;
            b0.v = *(const float4*)&Bs[k * 64 + tc * 8];
            b1.v = *(const float4*)&Bs[k * 64 + tc * 8 + 4];
            F4U a0, a1;
            a0.v = *(const float4*)&As[k * ASTR + tr * 8];
            a1.v = *(const float4*)&As[k * ASTR + tr * 8 + 4];
#pragma unroll
            for (int r = 0; r < 4; r++) {
                unsigned long long ad = dup2(a0.f[r]);
                ffma2(acc[r][0], ad, b0.u[0]);
                ffma2(acc[r][1], ad, b0.u[1]);
                ffma2(acc[r][2], ad, b1.u[0]);
                ffma2(acc[r][3], ad, b1.u[1]);
            }
#pragma unroll
            for (int r = 0; r < 4; r++) {
                unsigned long long ad = dup2(a1.f[r]);
                ffma2(acc[r + 4][0], ad, b0.u[0]);
                ffma2(acc[r + 4][1], ad, b0.u[1]);
                ffma2(acc[r + 4][2], ad, b1.u[0]);
                ffma2(acc[r + 4][3], ad, b1.u[1]);
            }
        }
    }

    float bj[8];
#pragma unroll
    for (int c = 0; c < 8; c++) bj[c] = bias[tc * 8 + c];
#pragma unroll
    for (int r = 0; r < 8; r++) {
        size_t base = (size_t)(m0 + tr * 8 + r) * LL + tc * 8;
#pragma unroll
        for (int c = 0; c < 4; c++) {
            float e0 = lo2(acc[r][c]) + bj[2 * c + 0];
            float e1 = hi2(acc[r][c]) + bj[2 * c + 1];
            out_em[base + 2 * c + 0] = e0;
            out_em[base + 2 * c + 1] = e1;
            Eo[base + 2 * c + 0] = expf(e0);
            Eo[base + 2 * c + 1] = expf(e1);
        }
    }
}

// ---------------------------------------------------------------------------
// CRF: linear-space forward scan. 64 blocks x 64 threads (j = tid).
//   w_j(t) = (sum_i w_i(t-1) * P_ij) * E_j(t),  P = exp(trans)
// Renormalize by w_0 every 8 steps; E double-buffered in smem.
// ---------------------------------------------------------------------------
__device__ __forceinline__ int tag_of(int x) {
    int t = (x == -100) ? 0 : x;
    return max(0, min(LL - 1, t));
}

__global__ __launch_bounds__(64) void crf_kernel(
    const float* __restrict__ em_all,   // raw emissions (= d_out+1)
    const float* __restrict__ E_all,    // g_E
    const int* __restrict__ mask,
    const int* __restrict__ labels,
    const float* __restrict__ start_t,
    const float* __restrict__ end_t,
    const float* __restrict__ trans)
{
    const int b = blockIdx.x;
    const int j = threadIdx.x;           // 0..63

    const float* em = em_all + (size_t)b * (SS * LL);
    const float* Ee = E_all + (size_t)b * (SS * LL);
    const int* msk = mask + b * SS;
    const int* lab = labels + (size_t)b * SS;

    __shared__ __align__(16) float4 u_sh[2][16];
    __shared__ __align__(16) float4 Esm[2][512];
    __shared__ float red[64];
    __shared__ int len_sh;
    __shared__ float num_sh;

    // ---- sequence length (contiguous prefix mask) ----
    int cnt = 0;
    for (int t = j; t < SS; t += 64) cnt += msk[t];
    red[j] = (float)cnt;
    __syncthreads();
#pragma unroll
    for (int s = 32; s > 0; s >>= 1) {
        if (j < s) red[j] += red[j + s];
        __syncthreads();
    }
    if (j == 0) len_sh = max(1, min(SS, (int)(red[0] + 0.5f)));
    __syncthreads();
    const int len = len_sh;

    // ---- numerator ----
    float nsum = 0.f;
    for (int t = 1 + j; t < len; t += 64) {
        int tp = tag_of(lab[t - 1]);
        int tc = tag_of(lab[t]);
        nsum += trans[tp * LL + tc] + em[t * LL + tc];
    }
    __syncthreads();
    red[j] = nsum;
    __syncthreads();
#pragma unroll
    for (int s = 32; s > 0; s >>= 1) {
        if (j < s) red[j] += red[j + s];
        __syncthreads();
    }
    if (j == 0) {
        int t0 = tag_of(lab[0]);
        int tl = tag_of(lab[len - 1]);
        num_sh = start_t[t0] + em[t0] + red[0] + end_t[tl];
    }

    // ---- P2[q] = (exp(trans[2q][j]), exp(trans[2q+1][j])) ----
    unsigned long long P2[32];
#pragma unroll
    for (int q = 0; q < 32; q++)
        P2[q] = pack2(__expf(trans[(2 * q) * LL + j]),
                      __expf(trans[(2 * q + 1) * LL + j]));

    // ---- E chunk 0 ----
#pragma unroll
    for (int p = 0; p < 8; p++) {
        int idx = p * 64 + j;
        Esm[0][idx] = *(const float4*)&Ee[(size_t)idx * 4];
    }
    __syncthreads();

    float w = __expf(start_t[j]) * ((const float*)Esm[0])[j];
    ((float*)u_sh[0])[j] = w;
    float logshift = 0.f;

    const int nchunks = (len + 31) >> 5;
    for (int ch = 0; ch < nchunks; ch++) {
        if (ch + 1 < nchunks) {
            int t0n = (ch + 1) << 5;
            int nq = min(512, (len - t0n) * 16);
#pragma unroll
            for (int p = 0; p < 8; p++) {
                int idx = p * 64 + j;
                if (idx < nq)
                    Esm[(ch + 1) & 1][idx] =
                        *(const float4*)&Ee[(size_t)t0n * 64 + (size_t)idx * 4];
            }
        }
        const float* Ep = (const float*)Esm[ch & 1];
        int tA = (ch == 0) ? 1 : (ch << 5);
        int tB = min(len, (ch + 1) << 5);

        for (int t = tA; t < tB; t++) {
            __syncthreads();
            const float4* U = u_sh[(t - 1) & 1];
            float u0 = ((const float*)U)[0];

            unsigned long long a0 = 0ull, a1 = 0ull, a2 = 0ull, a3 = 0ull;
#pragma unroll
            for (int q4 = 0; q4 < 16; q4 += 2) {
                F4U ua, ub;
                ua.v = U[q4];
                ub.v = U[q4 + 1];
                ffma2(a0, ua.u[0], P2[2 * q4 + 0]);
                ffma2(a1, ua.u[1], P2[2 * q4 + 1]);
                ffma2(a2, ub.u[0], P2[2 * q4 + 2]);
                ffma2(a3, ub.u[1], P2[2 * q4 + 3]);
            }
            float r = (lo2(a0) + hi2(a0)) + (lo2(a1) + hi2(a1)) +
                      (lo2(a2) + hi2(a2)) + (lo2(a3) + hi2(a3));
            float e = Ep[((t & 31) << 6) + j];
            float wn = r * e;
            if ((t & 7) == 0) {
                wn *= __frcp_rn(u0);
                logshift += __logf(u0);
            }
            w = wn;
            ((float*)u_sh[t & 1])[j] = w;
        }
        __syncthreads();
    }

    // ---- log Z ----
    red[j] = w * __expf(end_t[j]);
    __syncthreads();
#pragma unroll
    for (int s = 32; s > 0; s >>= 1) {
        if (j < s) red[j] += red[j + s];
        __syncthreads();
    }
    if (j == 0) {
        float log_z = __logf(red[0]) + logshift;
        g_llh[b] = num_sh - log_z;
    }
}

// ---------------------------------------------------------------------------
__global__ void loss_kernel(float* __restrict__ out) {
    int t = threadIdx.x;   // 32 threads
    float v = g_llh[t] + g_llh[t + 32];
#pragma unroll
    for (int o = 16; o > 0; o >>= 1) v += __shfl_down_sync(0xffffffffu, v, o);
    if (t == 0) out[0] = -v * (1.0f / BB);
}

// ---------------------------------------------------------------------------
extern "C" void kernel_launch(void* const* d_in, const int* in_sizes, int n_in,
                              void* d_out, int out_size)
{
    const float* hs      = (const float*)d_in[0];   // [B,S,H] f32
    const int* mask      = (const int*)d_in[1];     // [B,S]   i32
    const int* labels    = (const int*)d_in[2];     // [B,S]   i32
    const float* W       = (const float*)d_in[3];   // [H,L]   f32
    const float* bias    = (const float*)d_in[4];   // [L]
    const float* start_t = (const float*)d_in[5];   // [L]
    const float* end_t   = (const float*)d_in[6];   // [L]
    const float* trans   = (const float*)d_in[7];   // [L,L]
    float* out = (float*)d_out;    // out[0]=loss, out[1..]=emissions

    float* E_scratch = nullptr;
    cudaGetSymbolAddress((void**)&E_scratch, g_E);

    gemm_kernel<<<256, 128>>>(hs, W, bias, out + 1, E_scratch);
    crf_kernel<<<BB, 64>>>(out + 1, E_scratch, mask, labels,
                           start_t, end_t, trans);
    loss_kernel<<<1, 32>>>(out);
}